// round 5
// baseline (speedup 1.0000x reference)
#include <cuda_runtime.h>
#include <math.h>
#include <stdint.h>

#define D_NUM 1500
#define P_NUM 4500
#define NTOT  6000
#define EMB   128
#define CAP_DD 64
#define CAP_PP 128
#define DB (D_NUM*EMB)
#define PB (P_NUM*EMB)
#define MEGA_BLKS 296
#define MEGA_THREADS 256

// ---------------- scratch (static __device__, no allocs) ----------------
__device__ __align__(128) int g_idx2[D_NUM*CAP_DD]; __device__ int g_len2[D_NUM];
__device__ __align__(128) int g_idx4[D_NUM*CAP_DD]; __device__ int g_len4[D_NUM];
__device__ __align__(128) int g_idx3[P_NUM*CAP_PP]; __device__ int g_len3[P_NUM];
__device__ __align__(128) int g_idxR[D_NUM*CAP_PP]; __device__ int g_lenR[D_NUM];
__device__ __align__(128) int g_idxRT[P_NUM*CAP_DD]; __device__ int g_curRT[P_NUM];

__device__ float g_dinv2[D_NUM], g_cinv2[D_NUM];
__device__ float g_dinv3[P_NUM], g_cinv3[P_NUM];
__device__ float g_dinv4[D_NUM];
__device__ float g_dinvRd[D_NUM], g_cinvRd[D_NUM];
__device__ float g_dinvRp[P_NUM], g_cinvRp[P_NUM];

__device__ __align__(128) float g_dru_str[DB], g_pro_str[PB];
__device__ __align__(128) float g_nei2[DB],    g_nei3[PB];
__device__ __align__(128) float g_emb2[DB],    g_emb3[PB],  g_emb4[DB];
__device__ __align__(128) float g_curD[DB],    g_cur3[PB];
__device__ __align__(128) float g_x2a[DB], g_x2b[DB], g_x4a[DB], g_x4b[DB];
__device__ __align__(128) float g_x3a[PB], g_x3b[PB];
__device__ __align__(128) float g_acc2[DB], g_acc3[PB], g_acc4[DB];
__device__ __align__(128) float g_one_emb[DB], g_two_all[PB], g_one_all[DB], g_two_emb[PB];
__device__ __align__(128) float g_bd1[DB],  g_bp1[PB], g_bp2[PB];
__device__ __align__(128) float g_bdx[DB],  g_bpx[PB], g_bdy[DB];
__device__ __align__(128) float g_accd[DB], g_accp[PB];
__device__ __align__(128) float g_dru_int[DB], g_pro_int[PB];
__device__ __align__(128) float g_tmpp[PB], g_Wc[EMB*EMB];
__device__ __align__(128) float g_fin_d[DB], g_fin_p[PB];
__device__ float g_wdrug[D_NUM], g_wdrel[D_NUM], g_wdsim[D_NUM];
__device__ float g_wpro[P_NUM],  g_wprel[P_NUM];
__device__ double g_stats[2];
__device__ unsigned g_barcnt;

// ---------------- ELL extraction (all four blocks, one launch) -------------
// Register-prefetched: each thread issues all its loads (MLP=5) before testing.
__global__ void k_ell_all(const float* __restrict__ A) {
    const size_t NN = (size_t)NTOT * NTOT;
    int b = blockIdx.x;
    const float* base; int r, row0, col0, ncols, cap; int *idx, *len;
    if (b < 1500)      { base = A + 2*NN; r = b;        row0 = 0;     col0 = 0;     ncols = D_NUM; cap = CAP_DD; idx = g_idx2; len = g_len2; }
    else if (b < 6000) { base = A + 3*NN; r = b - 1500; row0 = D_NUM; col0 = D_NUM; ncols = P_NUM; cap = CAP_PP; idx = g_idx3; len = g_len3; }
    else if (b < 7500) { base = A + 4*NN; r = b - 6000; row0 = 0;     col0 = 0;     ncols = D_NUM; cap = CAP_DD; idx = g_idx4; len = g_len4; }
    else               { base = A;        r = b - 7500; row0 = 0;     col0 = D_NUM; ncols = P_NUM; cap = CAP_PP; idx = g_idxR; len = g_lenR; }

    const float4* row4 = (const float4*)(base + (size_t)(row0 + r) * NTOT + col0);
    int nv = ncols >> 2;               // 375 or 1125 float4s
    __shared__ int cnt;
    __shared__ int buf[160];
    if (threadIdx.x == 0) cnt = 0;
    __syncthreads();

    float4 v[5];
#pragma unroll
    for (int u = 0; u < 5; u++) {
        int i = threadIdx.x + u * 256;
        if (i < nv) v[u] = __ldg(&row4[i]);
    }
#pragma unroll
    for (int u = 0; u < 5; u++) {
        int i = threadIdx.x + u * 256;
        if (i < nv) {
            int c = i << 2;
            if (v[u].x == 1.0f) { int p = atomicAdd(&cnt, 1); if (p < 160) buf[p] = c; }
            if (v[u].y == 1.0f) { int p = atomicAdd(&cnt, 1); if (p < 160) buf[p] = c + 1; }
            if (v[u].z == 1.0f) { int p = atomicAdd(&cnt, 1); if (p < 160) buf[p] = c + 2; }
            if (v[u].w == 1.0f) { int p = atomicAdd(&cnt, 1); if (p < 160) buf[p] = c + 3; }
        }
    }
    __syncthreads();
    int L = min(cnt, cap);
    if (threadIdx.x == 0) {
        len[r] = L;
        for (int i = 1; i < L; i++) {      // deterministic column order
            int t = buf[i]; int j = i - 1;
            while (j >= 0 && buf[j] > t) { buf[j + 1] = buf[j]; j--; }
            buf[j + 1] = t;
        }
    }
    __syncthreads();
    for (int i = threadIdx.x; i < L; i += blockDim.x)
        idx[(size_t)r * cap + i] = buf[i];
}

// ---------------- megakernel device helpers ----------------

__device__ __forceinline__ void gsync(unsigned& target) {
    __syncthreads();
    if (threadIdx.x == 0) {
        __threadfence();
        atomicAdd(&g_barcnt, 1u);
        target += gridDim.x;
        unsigned v;
        do {
            asm volatile("ld.acquire.gpu.global.u32 %0, [%1];"
                         : "=r"(v) : "l"(&g_barcnt) : "memory");
        } while (v < target);
    }
    __syncthreads();
}

// C(n x 128) = A(n x k) @ W(k x 128) [+bias], optional dup C2/C3.
__device__ void gemm_dev(const float* A, int n, int k,
                         const float* W, bool wext, const float* bias,
                         float* C, float* C2, float* C3, float* sA) {
    int ntiles = (n + 15) >> 4;
    int col = threadIdx.x & 127;
    int half = threadIdx.x >> 7;
    for (int t = blockIdx.x; t < ntiles; t += gridDim.x) {
        int r0 = t << 4;
        __syncthreads();
        for (int i = threadIdx.x; i < (k << 4); i += MEGA_THREADS) {
            int rr = i / k, kk = i - rr * k;
            int gr = r0 + rr;
            sA[rr * k + kk] = (gr < n) ? A[(size_t)gr * k + kk] : 0.0f;
        }
        __syncthreads();
        float acc[8];
#pragma unroll
        for (int rr = 0; rr < 8; rr++) acc[rr] = 0.0f;
        const float* sAr = sA + (half << 3) * k;
        for (int kk = 0; kk < k; kk++) {
            float w = wext ? __ldg(&W[(size_t)kk * EMB + col]) : W[(size_t)kk * EMB + col];
#pragma unroll
            for (int rr = 0; rr < 8; rr++) acc[rr] += sAr[rr * k + kk] * w;
        }
        float b = bias ? __ldg(bias + col) : 0.0f;
#pragma unroll
        for (int rr = 0; rr < 8; rr++) {
            int gr = r0 + (half << 3) + rr;
            if (gr < n) {
                float v = acc[rr] + b;
                size_t o = (size_t)gr * EMB + col;
                C[o] = v;
                if (C2) C2[o] = v;
                if (C3) C3[o] = v;
            }
        }
    }
}

// ELL SpMM: warp per row, lane = one float4 of the 128-wide feature row.
__device__ void spmm_dev(const int* idx, const int* len, int cap,
                         const float* rs, const float* cs, const float* x,
                         float* out, float* acc, float* fin, float fscale,
                         const float* mixb, float* mixo, int n) {
    int nw = (gridDim.x * blockDim.x) >> 5;
    int gw = (blockIdx.x * blockDim.x + threadIdx.x) >> 5;
    int lane = threadIdx.x & 31;
    const float4* x4 = (const float4*)x;
    for (int r = gw; r < n; r += nw) {
        int L = len[r];
        float4 s = make_float4(0.f, 0.f, 0.f, 0.f);
        for (int p0 = 0; p0 < L; p0 += 32) {
            int j = 0; float f = 0.f;
            if (p0 + lane < L) {
                j = idx[(size_t)r * cap + p0 + lane];
                f = cs ? cs[j] : 1.0f;
            }
            int m = min(32, L - p0);
            int q = 0;
            for (; q + 4 <= m; q += 4) {
                int j0 = __shfl_sync(0xffffffffu, j, q);
                int j1 = __shfl_sync(0xffffffffu, j, q + 1);
                int j2 = __shfl_sync(0xffffffffu, j, q + 2);
                int j3 = __shfl_sync(0xffffffffu, j, q + 3);
                float f0 = __shfl_sync(0xffffffffu, f, q);
                float f1 = __shfl_sync(0xffffffffu, f, q + 1);
                float f2 = __shfl_sync(0xffffffffu, f, q + 2);
                float f3 = __shfl_sync(0xffffffffu, f, q + 3);
                float4 v0 = x4[(size_t)j0 * 32 + lane];
                float4 v1 = x4[(size_t)j1 * 32 + lane];
                float4 v2 = x4[(size_t)j2 * 32 + lane];
                float4 v3 = x4[(size_t)j3 * 32 + lane];
                s.x += f0 * v0.x + f1 * v1.x + f2 * v2.x + f3 * v3.x;
                s.y += f0 * v0.y + f1 * v1.y + f2 * v2.y + f3 * v3.y;
                s.z += f0 * v0.z + f1 * v1.z + f2 * v2.z + f3 * v3.z;
                s.w += f0 * v0.w + f1 * v1.w + f2 * v2.w + f3 * v3.w;
            }
            for (; q < m; q++) {
                int j0 = __shfl_sync(0xffffffffu, j, q);
                float f0 = __shfl_sync(0xffffffffu, f, q);
                float4 v0 = x4[(size_t)j0 * 32 + lane];
                s.x += f0 * v0.x; s.y += f0 * v0.y;
                s.z += f0 * v0.z; s.w += f0 * v0.w;
            }
        }
        float rr = rs[r];
        s.x *= rr; s.y *= rr; s.z *= rr; s.w *= rr;
        size_t o = (size_t)r * 32 + lane;
        if (out) ((float4*)out)[o] = s;
        if (acc) {
            float4 a = ((const float4*)acc)[o];
            a.x += s.x; a.y += s.y; a.z += s.z; a.w += s.w;
            ((float4*)acc)[o] = a;
            if (fin) {
                float4 ff = make_float4(a.x * fscale, a.y * fscale, a.z * fscale, a.w * fscale);
                ((float4*)fin)[o] = ff;
            }
        }
        if (mixo) {
            float4 mb = ((const float4*)mixb)[o];
            float4 mo = make_float4(0.8f * mb.x + 0.2f * s.x, 0.8f * mb.y + 0.2f * s.y,
                                    0.8f * mb.z + 0.2f * s.z, 0.8f * mb.w + 0.2f * s.w);
            ((float4*)mixo)[o] = mo;
        }
    }
}

// s[r] = sum_c relu(emb[r]@W + B)[c]*H[c]; 16-row tiles.
__device__ void att_dev(const float* emb, const float* W, const float* B,
                        const float* H, float* s, int n, float* sE) {
    int ntiles = (n + 15) >> 4;
    int col = threadIdx.x & 127;
    int half = threadIdx.x >> 7;
    for (int t = blockIdx.x; t < ntiles; t += gridDim.x) {
        int r0 = t << 4;
        __syncthreads();
        for (int i = threadIdx.x; i < 16 * 128; i += MEGA_THREADS) {
            int rr = i >> 7, kk = i & 127;
            int gr = r0 + rr;
            sE[i] = (gr < n) ? emb[(size_t)gr * EMB + kk] : 0.0f;
        }
        __syncthreads();
        float acc[8];
#pragma unroll
        for (int rr = 0; rr < 8; rr++) acc[rr] = 0.0f;
        const float* sEr = sE + (half << 3) * 128;
#pragma unroll 4
        for (int kk = 0; kk < 128; kk++) {
            float w = __ldg(&W[kk * EMB + col]);
#pragma unroll
            for (int rr = 0; rr < 8; rr++) acc[rr] += sEr[rr * 128 + kk] * w;
        }
        float bb = __ldg(B + col), hh = __ldg(H + col);
        __syncthreads();
#pragma unroll
        for (int rr = 0; rr < 8; rr++)
            sE[((half << 3) + rr) * 128 + col] = fmaxf(acc[rr] + bb, 0.0f) * hh;
        __syncthreads();
        int wid = threadIdx.x >> 5, lane = threadIdx.x & 31;
#pragma unroll
        for (int i = 0; i < 2; i++) {
            int row = wid * 2 + i;
            float v = sE[row * 128 + lane] + sE[row * 128 + lane + 32]
                    + sE[row * 128 + lane + 64] + sE[row * 128 + lane + 96];
            for (int off = 16; off; off >>= 1) v += __shfl_down_sync(0xffffffffu, v, off);
            if (lane == 0 && r0 + row < n) s[r0 + row] = v;
        }
    }
}

__device__ void ls_dev(float* s, int n, float* sh) {
    int t = threadIdx.x;
    float m = -1e30f;
    for (int i = t; i < n; i += MEGA_THREADS) m = fmaxf(m, s[i]);
    sh[t] = m; __syncthreads();
    for (int o = 128; o; o >>= 1) { if (t < o) sh[t] = fmaxf(sh[t], sh[t + o]); __syncthreads(); }
    float mall = sh[0]; __syncthreads();
    float sum = 0.0f;
    for (int i = t; i < n; i += MEGA_THREADS) sum += expf(s[i] - mall);
    sh[t] = sum; __syncthreads();
    for (int o = 128; o; o >>= 1) { if (t < o) sh[t] += sh[t + o]; __syncthreads(); }
    float lse = mall + logf(sh[0]);
    __syncthreads();
    for (int i = t; i < n; i += MEGA_THREADS) s[i] -= lse;
}

// ---------------- the megakernel: rt_fill ... combine in ONE launch --------
__global__ void __launch_bounds__(MEGA_THREADS, 2) k_mega(
    const float* __restrict__ drug_structure, const float* __restrict__ protein_structure,
    const float* __restrict__ lin_drug_w, const float* __restrict__ lin_drug_b,
    const float* __restrict__ lin_pro_w, const float* __restrict__ lin_pro_b,
    const float* __restrict__ p_weight, const float* __restrict__ d_weight_i,
    const float* __restrict__ pd_weight_p, const float* __restrict__ pd_weight_d,
    const float* __restrict__ dp_weight_p,
    const float* __restrict__ WA_drug, const float* __restrict__ BA_drug, const float* __restrict__ HA_drug,
    const float* __restrict__ WB_drug, const float* __restrict__ BB_drug, const float* __restrict__ HB_drug,
    const float* __restrict__ WA_pro, const float* __restrict__ BA_pro, const float* __restrict__ HA_pro,
    const float* __restrict__ WB_pro, const float* __restrict__ BB_pro, const float* __restrict__ HB_pro,
    const float* __restrict__ WA_sim, const float* __restrict__ BA_sim, const float* __restrict__ HA_sim) {
    __shared__ float sbuf[16 * 512];
    unsigned target = 0;

    // ---- P1: build R^T
    {
        int nw = (gridDim.x * blockDim.x) >> 5;
        int gw = (blockIdx.x * blockDim.x + threadIdx.x) >> 5;
        int lane = threadIdx.x & 31;
        for (int r = gw; r < D_NUM; r += nw) {
            int L = g_lenR[r];
            for (int p = lane; p < L; p += 32) {
                int c = g_idxR[r * CAP_PP + p];
                int pos = atomicAdd(&g_curRT[c], 1);
                if (pos < CAP_DD) g_idxRT[c * CAP_DD + pos] = r;
            }
        }
    }
    gsync(target);

    // ---- P2: sort R^T rows + all degree scales
    {
        int i = blockIdx.x * blockDim.x + threadIdx.x;
        if (i < D_NUM) {
            int d;
            d = g_len2[i]; g_dinv2[i] = d > 0 ? rsqrtf((float)d) : 0.0f;
                           g_cinv2[i] = d > 0 ? 1.0f / (float)d : 0.0f;
            d = g_len4[i]; g_dinv4[i] = d > 0 ? rsqrtf((float)d) : 0.0f;
            d = g_lenR[i]; g_dinvRd[i] = d > 0 ? rsqrtf((float)d) : 0.0f;
                           g_cinvRd[i] = d > 0 ? 1.0f / (float)d : 0.0f;
        }
        if (i < P_NUM) {
            int d = g_len3[i];
            g_dinv3[i] = d > 0 ? rsqrtf((float)d) : 0.0f;
            g_cinv3[i] = d > 0 ? 1.0f / (float)d : 0.0f;
            int L = min(g_curRT[i], CAP_DD);
            g_curRT[i] = L;
            int* a = &g_idxRT[i * CAP_DD];
            for (int q = 1; q < L; q++) {
                int v = a[q]; int jj = q - 1;
                while (jj >= 0 && a[jj] > v) { a[jj + 1] = a[jj]; jj--; }
                a[jj + 1] = v;
            }
            g_dinvRp[i] = L > 0 ? rsqrtf((float)L) : 0.0f;
            g_cinvRp[i] = L > 0 ? 1.0f / (float)L : 0.0f;
        }
    }
    gsync(target);

    // ---- P3: feature lifts + Wc
    gemm_dev(drug_structure, D_NUM, 160, lin_drug_w, true, lin_drug_b, g_dru_str, 0, 0, sbuf);
    gemm_dev(protein_structure, P_NUM, 512, lin_pro_w, true, lin_pro_b, g_pro_str, 0, 0, sbuf);
    gemm_dev(dp_weight_p, 128, 128, pd_weight_d, true, 0, g_Wc, 0, 0, sbuf);
    gsync(target);

    // ---- P4: tower-input GEMMs (+acc inits) and neighbor means
    gemm_dev(g_dru_str, D_NUM, 128, d_weight_i, true, 0, g_curD, g_acc2, g_acc4, sbuf);
    gemm_dev(g_pro_str, P_NUM, 128, p_weight, true, 0, g_cur3, g_acc3, 0, sbuf);
    gemm_dev(g_dru_str, D_NUM, 128, pd_weight_d, true, 0, g_one_emb, g_accd, 0, sbuf);
    gemm_dev(g_pro_str, P_NUM, 128, pd_weight_p, true, 0, g_two_emb, g_accp, 0, sbuf);
    spmm_dev(g_idx2, g_len2, CAP_DD, g_cinv2, 0, g_dru_str, g_nei2, 0, 0, 0.f, 0, 0, D_NUM);
    spmm_dev(g_idx3, g_len3, CAP_PP, g_cinv3, 0, g_pro_str, g_nei3, 0, 0, 0.f, 0, 0, P_NUM);
    gsync(target);

    // ---- P5: GCN layer 1 + cross-domain neighbor means with fused mix
    spmm_dev(g_idx2, g_len2, CAP_DD, g_dinv2, g_dinv2, g_curD, g_x2a, g_acc2, 0, 0.f, 0, 0, D_NUM);
    spmm_dev(g_idx3, g_len3, CAP_PP, g_dinv3, g_dinv3, g_cur3, g_x3a, g_acc3, 0, 0.f, 0, 0, P_NUM);
    spmm_dev(g_idx4, g_len4, CAP_DD, g_dinv4, g_dinv4, g_curD, g_x4a, g_acc4, 0, 0.f, 0, 0, D_NUM);
    spmm_dev(g_idxR, g_lenR, CAP_PP, g_cinvRd, 0, g_nei3, 0, 0, 0, 0.f, g_dru_str, g_one_all, D_NUM);
    spmm_dev(g_idxRT, g_curRT, CAP_DD, g_cinvRp, 0, g_nei2, 0, 0, 0, 0.f, g_pro_str, g_tmpp, P_NUM);
    gsync(target);

    // ---- P6: GCN layer 2 + two_all GEMM
    spmm_dev(g_idx2, g_len2, CAP_DD, g_dinv2, g_dinv2, g_x2a, g_x2b, g_acc2, 0, 0.f, 0, 0, D_NUM);
    spmm_dev(g_idx3, g_len3, CAP_PP, g_dinv3, g_dinv3, g_x3a, g_x3b, g_acc3, 0, 0.f, 0, 0, P_NUM);
    spmm_dev(g_idx4, g_len4, CAP_DD, g_dinv4, g_dinv4, g_x4a, g_x4b, g_acc4, 0, 0.f, 0, 0, D_NUM);
    gemm_dev(g_tmpp, P_NUM, 128, g_Wc, false, 0, g_two_all, 0, 0, sbuf);
    gsync(target);

    // ---- P7: GCN layer 3 (finalize towers) + bipartite step 1
    spmm_dev(g_idx2, g_len2, CAP_DD, g_dinv2, g_dinv2, g_x2b, 0, g_acc2, g_emb2, 0.25f, 0, 0, D_NUM);
    spmm_dev(g_idx3, g_len3, CAP_PP, g_dinv3, g_dinv3, g_x3b, 0, g_acc3, g_emb3, 0.25f, 0, 0, P_NUM);
    spmm_dev(g_idx4, g_len4, CAP_DD, g_dinv4, g_dinv4, g_x4b, 0, g_acc4, g_emb4, 0.25f, 0, 0, D_NUM);
    spmm_dev(g_idxR, g_lenR, CAP_PP, g_dinvRd, g_dinvRp, g_two_all, g_bd1, g_accd, 0, 0.f, 0, 0, D_NUM);
    spmm_dev(g_idxRT, g_curRT, CAP_DD, g_dinvRp, g_dinvRd, g_one_emb, g_bp1, 0, 0, 0.f, 0, 0, P_NUM);
    spmm_dev(g_idxRT, g_curRT, CAP_DD, g_dinvRp, g_dinvRd, g_one_all, g_bpx, g_accp, 0, 0.f, 0, 0, P_NUM);
    spmm_dev(g_idxR, g_lenR, CAP_PP, g_dinvRd, g_dinvRp, g_two_emb, g_bdx, 0, 0, 0.f, 0, 0, D_NUM);
    gsync(target);

    // ---- P8: bipartite step 2 + the three tower attention heads (overlap)
    spmm_dev(g_idxRT, g_curRT, CAP_DD, g_dinvRp, g_dinvRd, g_bd1, g_bp2, 0, 0, 0.f, 0, 0, P_NUM);
    spmm_dev(g_idxR, g_lenR, CAP_PP, g_dinvRd, g_dinvRp, g_bp1, 0, g_accd, 0, 0.f, 0, 0, D_NUM);
    spmm_dev(g_idxRT, g_curRT, CAP_DD, g_dinvRp, g_dinvRd, g_bdx, 0, g_accp, 0, 0.f, 0, 0, P_NUM);
    spmm_dev(g_idxR, g_lenR, CAP_PP, g_dinvRd, g_dinvRp, g_bpx, g_bdy, 0, 0, 0.f, 0, 0, D_NUM);
    att_dev(g_emb2, WB_drug, BB_drug, HB_drug, g_wdrel, D_NUM, sbuf);
    att_dev(g_emb3, WB_pro, BB_pro, HB_pro, g_wprel, P_NUM, sbuf);
    att_dev(g_emb4, WA_sim, BA_sim, HA_sim, g_wdsim, D_NUM, sbuf);
    gsync(target);

    // ---- P9: bipartite step 3 (finalize dru_int / pro_int)
    spmm_dev(g_idxR, g_lenR, CAP_PP, g_dinvRd, g_dinvRp, g_bp2, 0, g_accd, g_dru_int, 0.25f, 0, 0, D_NUM);
    spmm_dev(g_idxRT, g_curRT, CAP_DD, g_dinvRp, g_dinvRd, g_bdy, 0, g_accp, g_pro_int, 0.25f, 0, 0, P_NUM);
    gsync(target);

    // ---- P10: remaining attention heads (need P9)
    att_dev(g_dru_int, WA_drug, BA_drug, HA_drug, g_wdrug, D_NUM, sbuf);
    att_dev(g_pro_int, WA_pro, BA_pro, HA_pro, g_wpro, P_NUM, sbuf);
    gsync(target);

    // ---- P11: log-softmax (5 heads, 5 blocks)
    if (blockIdx.x < 5) {
        float* s; int n;
        switch (blockIdx.x) {
            case 0: s = g_wdrug; n = D_NUM; break;
            case 1: s = g_wpro;  n = P_NUM; break;
            case 2: s = g_wdrel; n = D_NUM; break;
            case 3: s = g_wprel; n = P_NUM; break;
            default:s = g_wdsim; n = D_NUM; break;
        }
        ls_dev(s, n, sbuf);
    }
    gsync(target);

    // ---- P12: weighted combine
    {
        int stride = gridDim.x * blockDim.x;
        for (int i = blockIdx.x * blockDim.x + threadIdx.x; i < DB + PB; i += stride) {
            if (i < DB) {
                int r = i >> 7;
                float wa = g_wdrug[r], wb = g_wdrel[r], wc = g_wdsim[r];
                float a = wa / (wa + wb + wc);
                float b = wb / (a + wb + wc);
                float c = 1.0f - a - b;
                g_fin_d[i] = a * g_dru_int[i] + b * g_emb2[i] + c * g_emb4[i];
            } else {
                int j = i - DB;
                int r = j >> 7;
                float wa = g_wpro[r], wb = g_wprel[r];
                float pa = wa / (wa + wb);
                g_fin_p[j] = pa * g_pro_int[j] + (1.0f - pa) * g_emb3[j];
            }
        }
    }
}

// ---------------- final GEMM (writes y directly to out) --------------------
__global__ void __launch_bounds__(256) k_final_gemm(float* __restrict__ out) {
    __shared__ __align__(16) float sA[32 * 132];
    __shared__ __align__(16) float sB[32 * 132];
    int bi = blockIdx.y * 128, bj = blockIdx.x * 128;
    int t = threadIdx.x;
    int tx = t & 15, ty = t >> 4;
    int m0 = ty * 8, n0 = tx * 8;
    float acc[8][8];
#pragma unroll
    for (int i = 0; i < 8; i++)
#pragma unroll
        for (int j = 0; j < 8; j++) acc[i][j] = 0.0f;

    for (int k0 = 0; k0 < EMB; k0 += 32) {
#pragma unroll
        for (int it = 0; it < 4; it++) {
            int e = t + it * 256;
            int rr = e >> 3, kv = e & 7;
            int gi = bi + rr, gj = bj + rr;
            float4 va = (gi < D_NUM) ? *(const float4*)&g_fin_d[(size_t)gi * EMB + k0 + kv * 4]
                                     : make_float4(0.f, 0.f, 0.f, 0.f);
            float4 vb = (gj < P_NUM) ? *(const float4*)&g_fin_p[(size_t)gj * EMB + k0 + kv * 4]
                                     : make_float4(0.f, 0.f, 0.f, 0.f);
            sA[(kv * 4 + 0) * 132 + rr] = va.x;
            sA[(kv * 4 + 1) * 132 + rr] = va.y;
            sA[(kv * 4 + 2) * 132 + rr] = va.z;
            sA[(kv * 4 + 3) * 132 + rr] = va.w;
            sB[(kv * 4 + 0) * 132 + rr] = vb.x;
            sB[(kv * 4 + 1) * 132 + rr] = vb.y;
            sB[(kv * 4 + 2) * 132 + rr] = vb.z;
            sB[(kv * 4 + 3) * 132 + rr] = vb.w;
        }
        __syncthreads();
#pragma unroll
        for (int kk = 0; kk < 32; kk++) {
            const float* pa = &sA[kk * 132 + m0];
            const float* pb = &sB[kk * 132 + n0];
            float4 a0 = *(const float4*)pa;
            float4 a1 = *(const float4*)(pa + 4);
            float4 b0 = *(const float4*)pb;
            float4 b1 = *(const float4*)(pb + 4);
            float ra[8] = {a0.x, a0.y, a0.z, a0.w, a1.x, a1.y, a1.z, a1.w};
            float rb[8] = {b0.x, b0.y, b0.z, b0.w, b1.x, b1.y, b1.z, b1.w};
#pragma unroll
            for (int i = 0; i < 8; i++)
#pragma unroll
                for (int j = 0; j < 8; j++) acc[i][j] += ra[i] * rb[j];
        }
        __syncthreads();
    }
    double ls = 0.0, lq = 0.0;
#pragma unroll
    for (int i = 0; i < 8; i++) {
        int gi = bi + m0 + i;
        if (gi < D_NUM) {
#pragma unroll
            for (int j = 0; j < 8; j++) {
                int gj = bj + n0 + j;
                if (gj < P_NUM) {
                    float v = acc[i][j];
                    out[(size_t)gi * P_NUM + gj] = v;
                    ls += v;
                    lq += (double)v * v;
                }
            }
        }
    }
    __shared__ double sd[256];
    sd[t] = ls; __syncthreads();
    for (int o = 128; o; o >>= 1) { if (t < o) sd[t] += sd[t + o]; __syncthreads(); }
    if (t == 0) atomicAdd(&g_stats[0], sd[0]);
    __syncthreads();
    sd[t] = lq; __syncthreads();
    for (int o = 128; o; o >>= 1) { if (t < o) sd[t] += sd[t + o]; __syncthreads(); }
    if (t == 0) atomicAdd(&g_stats[1], sd[0]);
}

// In-place standardize + sigmoid on out (fast intrinsics).
__global__ void k_finalize(float* __restrict__ out) {
    const double n = (double)D_NUM * (double)P_NUM;
    double sum = g_stats[0], sq = g_stats[1];
    double mean = sum / n;
    double var = (sq - sum * sum / n) / (n - 1.0);
    float istd = (float)(1.0 / sqrt(var));
    float mu = (float)mean;
    const size_t N4 = (size_t)D_NUM * P_NUM / 4;
    float4* o4 = (float4*)out;
    size_t i0 = (size_t)blockIdx.x * blockDim.x + threadIdx.x;
    size_t stride = (size_t)gridDim.x * blockDim.x;
    for (size_t i = i0; i < N4; i += stride) {
        float4 v = o4[i];
        float4 o;
        o.x = __frcp_rn(1.0f + __expf(-(v.x - mu) * istd));
        o.y = __frcp_rn(1.0f + __expf(-(v.y - mu) * istd));
        o.z = __frcp_rn(1.0f + __expf(-(v.z - mu) * istd));
        o.w = __frcp_rn(1.0f + __expf(-(v.w - mu) * istd));
        o4[i] = o;
    }
}

// ---------------- host launcher ----------------
extern "C" void kernel_launch(void* const* d_in, const int* in_sizes, int n_in,
                              void* d_out, int out_size) {
    const float* A                 = (const float*)d_in[0];
    const float* drug_structure    = (const float*)d_in[1];
    const float* protein_structure = (const float*)d_in[2];
    const float* lin_drug_w = (const float*)d_in[3];
    const float* lin_drug_b = (const float*)d_in[4];
    const float* lin_pro_w  = (const float*)d_in[5];
    const float* lin_pro_b  = (const float*)d_in[6];
    const float* p_weight   = (const float*)d_in[7];
    const float* d_weight_i = (const float*)d_in[8];
    const float* pd_weight_p = (const float*)d_in[9];
    const float* pd_weight_d = (const float*)d_in[10];
    const float* dp_weight_p = (const float*)d_in[11];
    const float* WA_drug = (const float*)d_in[12];
    const float* BA_drug = (const float*)d_in[13];
    const float* HA_drug = (const float*)d_in[14];
    const float* WB_drug = (const float*)d_in[15];
    const float* BB_drug = (const float*)d_in[16];
    const float* HB_drug = (const float*)d_in[17];
    const float* WA_pro = (const float*)d_in[18];
    const float* BA_pro = (const float*)d_in[19];
    const float* HA_pro = (const float*)d_in[20];
    const float* WB_pro = (const float*)d_in[21];
    const float* BB_pro = (const float*)d_in[22];
    const float* HB_pro = (const float*)d_in[23];
    const float* WA_sim = (const float*)d_in[24];
    const float* BA_sim = (const float*)d_in[25];
    const float* HA_sim = (const float*)d_in[26];
    float* out = (float*)d_out;
    (void)in_sizes; (void)n_in; (void)out_size;

    void* tp;
    cudaGetSymbolAddress(&tp, g_curRT);  void* p_curRT  = tp;
    cudaGetSymbolAddress(&tp, g_stats);  void* p_stats  = tp;
    cudaGetSymbolAddress(&tp, g_barcnt); void* p_barcnt = tp;

    cudaMemsetAsync(p_curRT, 0, P_NUM * sizeof(int), 0);
    cudaMemsetAsync(p_stats, 0, 2 * sizeof(double), 0);
    cudaMemsetAsync(p_barcnt, 0, sizeof(unsigned), 0);

    k_ell_all<<<9000, 256>>>(A);

    k_mega<<<MEGA_BLKS, MEGA_THREADS>>>(
        drug_structure, protein_structure,
        lin_drug_w, lin_drug_b, lin_pro_w, lin_pro_b,
        p_weight, d_weight_i, pd_weight_p, pd_weight_d, dp_weight_p,
        WA_drug, BA_drug, HA_drug,
        WB_drug, BB_drug, HB_drug,
        WA_pro, BA_pro, HA_pro,
        WB_pro, BB_pro, HB_pro,
        WA_sim, BA_sim, HA_sim);

    dim3 fg((P_NUM + 127) / 128, (D_NUM + 127) / 128);
    k_final_gemm<<<fg, 256>>>(out);
    k_finalize<<<4096, 256>>>(out);
}

// round 6
// speedup vs baseline: 1.1160x; 1.1160x over previous
#include <cuda_runtime.h>
#include <math.h>
#include <stdint.h>

#define D_NUM 1500
#define P_NUM 4500
#define NTOT  6000
#define EMB   128
#define CAP_DD 64
#define CAP_PP 128
#define DB (D_NUM*EMB)
#define PB (P_NUM*EMB)
#define MEGA_BLKS 296
#define MEGA_THREADS 256

// ---------------- scratch (static __device__, no allocs) ----------------
__device__ __align__(128) int g_idx2[D_NUM*CAP_DD]; __device__ int g_len2[D_NUM];
__device__ __align__(128) int g_idx4[D_NUM*CAP_DD]; __device__ int g_len4[D_NUM];
__device__ __align__(128) int g_idx3[P_NUM*CAP_PP]; __device__ int g_len3[P_NUM];
__device__ __align__(128) int g_idxR[D_NUM*CAP_PP]; __device__ int g_lenR[D_NUM];
__device__ __align__(128) int g_idxRT[P_NUM*CAP_DD]; __device__ int g_curRT[P_NUM];

__device__ float g_dinv2[D_NUM], g_cinv2[D_NUM];
__device__ float g_dinv3[P_NUM], g_cinv3[P_NUM];
__device__ float g_dinv4[D_NUM];
__device__ float g_dinvRd[D_NUM], g_cinvRd[D_NUM];
__device__ float g_dinvRp[P_NUM], g_cinvRp[P_NUM];

__device__ __align__(128) float g_dru_str[DB], g_pro_str[PB];
__device__ __align__(128) float g_nei2[DB],    g_nei3[PB];
__device__ __align__(128) float g_emb2[DB],    g_emb3[PB],  g_emb4[DB];
__device__ __align__(128) float g_curD[DB],    g_cur3[PB];
__device__ __align__(128) float g_x2a[DB], g_x2b[DB], g_x4a[DB], g_x4b[DB];
__device__ __align__(128) float g_x3a[PB], g_x3b[PB];
__device__ __align__(128) float g_acc2[DB], g_acc3[PB], g_acc4[DB];
__device__ __align__(128) float g_one_emb[DB], g_two_all[PB], g_one_all[DB], g_two_emb[PB];
__device__ __align__(128) float g_bd1[DB],  g_bp1[PB], g_bp2[PB];
__device__ __align__(128) float g_bdx[DB],  g_bpx[PB], g_bdy[DB];
__device__ __align__(128) float g_accd[DB], g_accp[PB];
__device__ __align__(128) float g_dru_int[DB], g_pro_int[PB];
__device__ __align__(128) float g_tmpp[PB], g_Wc[EMB*EMB];
__device__ __align__(128) float g_fin_d[DB], g_fin_p[PB];
__device__ float g_wdrug[D_NUM], g_wdrel[D_NUM], g_wdsim[D_NUM];
__device__ float g_wpro[P_NUM],  g_wprel[P_NUM];
__device__ __align__(128) float g_gd[EMB*EMB], g_gp[EMB*EMB];
__device__ float g_sd[EMB], g_sp[EMB];
__device__ float2 g_musig;
__device__ unsigned g_barcnt;

// ---------------- ELL extraction (all four blocks, one launch) -------------
__global__ void k_ell_all(const float* __restrict__ A) {
    const size_t NN = (size_t)NTOT * NTOT;
    int b = blockIdx.x;
    const float* base; int r, row0, col0, ncols, cap; int *idx, *len;
    if (b < 1500)      { base = A + 2*NN; r = b;        row0 = 0;     col0 = 0;     ncols = D_NUM; cap = CAP_DD; idx = g_idx2; len = g_len2; }
    else if (b < 6000) { base = A + 3*NN; r = b - 1500; row0 = D_NUM; col0 = D_NUM; ncols = P_NUM; cap = CAP_PP; idx = g_idx3; len = g_len3; }
    else if (b < 7500) { base = A + 4*NN; r = b - 6000; row0 = 0;     col0 = 0;     ncols = D_NUM; cap = CAP_DD; idx = g_idx4; len = g_len4; }
    else               { base = A;        r = b - 7500; row0 = 0;     col0 = D_NUM; ncols = P_NUM; cap = CAP_PP; idx = g_idxR; len = g_lenR; }

    const float4* row4 = (const float4*)(base + (size_t)(row0 + r) * NTOT + col0);
    int nv = ncols >> 2;
    __shared__ int cnt;
    __shared__ int buf[160];
    if (threadIdx.x == 0) cnt = 0;
    __syncthreads();

    float4 v[5];
#pragma unroll
    for (int u = 0; u < 5; u++) {
        int i = threadIdx.x + u * 256;
        if (i < nv) v[u] = __ldg(&row4[i]);
    }
#pragma unroll
    for (int u = 0; u < 5; u++) {
        int i = threadIdx.x + u * 256;
        if (i < nv) {
            int c = i << 2;
            if (v[u].x == 1.0f) { int p = atomicAdd(&cnt, 1); if (p < 160) buf[p] = c; }
            if (v[u].y == 1.0f) { int p = atomicAdd(&cnt, 1); if (p < 160) buf[p] = c + 1; }
            if (v[u].z == 1.0f) { int p = atomicAdd(&cnt, 1); if (p < 160) buf[p] = c + 2; }
            if (v[u].w == 1.0f) { int p = atomicAdd(&cnt, 1); if (p < 160) buf[p] = c + 3; }
        }
    }
    __syncthreads();
    int L = min(cnt, cap);
    if (threadIdx.x == 0) {
        len[r] = L;
        for (int i = 1; i < L; i++) {
            int t = buf[i]; int j = i - 1;
            while (j >= 0 && buf[j] > t) { buf[j + 1] = buf[j]; j--; }
            buf[j + 1] = t;
        }
    }
    __syncthreads();
    for (int i = threadIdx.x; i < L; i += blockDim.x)
        idx[(size_t)r * cap + i] = buf[i];
}

// ---------------- megakernel device helpers ----------------

__device__ __forceinline__ void gsync(unsigned& target) {
    __syncthreads();
    if (threadIdx.x == 0) {
        __threadfence();
        atomicAdd(&g_barcnt, 1u);
        target += gridDim.x;
        unsigned v;
        do {
            asm volatile("ld.acquire.gpu.global.u32 %0, [%1];"
                         : "=r"(v) : "l"(&g_barcnt) : "memory");
        } while (v < target);
    }
    __syncthreads();
}

__device__ void gemm_dev(const float* A, int n, int k,
                         const float* W, bool wext, const float* bias,
                         float* C, float* C2, float* C3, float* sA) {
    int ntiles = (n + 15) >> 4;
    int col = threadIdx.x & 127;
    int half = threadIdx.x >> 7;
    for (int t = blockIdx.x; t < ntiles; t += gridDim.x) {
        int r0 = t << 4;
        __syncthreads();
        for (int i = threadIdx.x; i < (k << 4); i += MEGA_THREADS) {
            int rr = i / k, kk = i - rr * k;
            int gr = r0 + rr;
            sA[rr * k + kk] = (gr < n) ? A[(size_t)gr * k + kk] : 0.0f;
        }
        __syncthreads();
        float acc[8];
#pragma unroll
        for (int rr = 0; rr < 8; rr++) acc[rr] = 0.0f;
        const float* sAr = sA + (half << 3) * k;
        for (int kk = 0; kk < k; kk++) {
            float w = wext ? __ldg(&W[(size_t)kk * EMB + col]) : W[(size_t)kk * EMB + col];
#pragma unroll
            for (int rr = 0; rr < 8; rr++) acc[rr] += sAr[rr * k + kk] * w;
        }
        float b = bias ? __ldg(bias + col) : 0.0f;
#pragma unroll
        for (int rr = 0; rr < 8; rr++) {
            int gr = r0 + (half << 3) + rr;
            if (gr < n) {
                float v = acc[rr] + b;
                size_t o = (size_t)gr * EMB + col;
                C[o] = v;
                if (C2) C2[o] = v;
                if (C3) C3[o] = v;
            }
        }
    }
}

__device__ void spmm_dev(const int* idx, const int* len, int cap,
                         const float* rs, const float* cs, const float* x,
                         float* out, float* acc, float* fin, float fscale,
                         const float* mixb, float* mixo, int n) {
    int nw = (gridDim.x * blockDim.x) >> 5;
    int gw = (blockIdx.x * blockDim.x + threadIdx.x) >> 5;
    int lane = threadIdx.x & 31;
    const float4* x4 = (const float4*)x;
    for (int r = gw; r < n; r += nw) {
        int L = len[r];
        float4 s = make_float4(0.f, 0.f, 0.f, 0.f);
        for (int p0 = 0; p0 < L; p0 += 32) {
            int j = 0; float f = 0.f;
            if (p0 + lane < L) {
                j = idx[(size_t)r * cap + p0 + lane];
                f = cs ? cs[j] : 1.0f;
            }
            int m = min(32, L - p0);
            int q = 0;
            for (; q + 4 <= m; q += 4) {
                int j0 = __shfl_sync(0xffffffffu, j, q);
                int j1 = __shfl_sync(0xffffffffu, j, q + 1);
                int j2 = __shfl_sync(0xffffffffu, j, q + 2);
                int j3 = __shfl_sync(0xffffffffu, j, q + 3);
                float f0 = __shfl_sync(0xffffffffu, f, q);
                float f1 = __shfl_sync(0xffffffffu, f, q + 1);
                float f2 = __shfl_sync(0xffffffffu, f, q + 2);
                float f3 = __shfl_sync(0xffffffffu, f, q + 3);
                float4 v0 = x4[(size_t)j0 * 32 + lane];
                float4 v1 = x4[(size_t)j1 * 32 + lane];
                float4 v2 = x4[(size_t)j2 * 32 + lane];
                float4 v3 = x4[(size_t)j3 * 32 + lane];
                s.x += f0 * v0.x + f1 * v1.x + f2 * v2.x + f3 * v3.x;
                s.y += f0 * v0.y + f1 * v1.y + f2 * v2.y + f3 * v3.y;
                s.z += f0 * v0.z + f1 * v1.z + f2 * v2.z + f3 * v3.z;
                s.w += f0 * v0.w + f1 * v1.w + f2 * v2.w + f3 * v3.w;
            }
            for (; q < m; q++) {
                int j0 = __shfl_sync(0xffffffffu, j, q);
                float f0 = __shfl_sync(0xffffffffu, f, q);
                float4 v0 = x4[(size_t)j0 * 32 + lane];
                s.x += f0 * v0.x; s.y += f0 * v0.y;
                s.z += f0 * v0.z; s.w += f0 * v0.w;
            }
        }
        float rr = rs[r];
        s.x *= rr; s.y *= rr; s.z *= rr; s.w *= rr;
        size_t o = (size_t)r * 32 + lane;
        if (out) ((float4*)out)[o] = s;
        if (acc) {
            float4 a = ((const float4*)acc)[o];
            a.x += s.x; a.y += s.y; a.z += s.z; a.w += s.w;
            ((float4*)acc)[o] = a;
            if (fin) {
                float4 ff = make_float4(a.x * fscale, a.y * fscale, a.z * fscale, a.w * fscale);
                ((float4*)fin)[o] = ff;
            }
        }
        if (mixo) {
            float4 mb = ((const float4*)mixb)[o];
            float4 mo = make_float4(0.8f * mb.x + 0.2f * s.x, 0.8f * mb.y + 0.2f * s.y,
                                    0.8f * mb.z + 0.2f * s.z, 0.8f * mb.w + 0.2f * s.w);
            ((float4*)mixo)[o] = mo;
        }
    }
}

__device__ void att_dev(const float* emb, const float* W, const float* B,
                        const float* H, float* s, int n, float* sE) {
    int ntiles = (n + 15) >> 4;
    int col = threadIdx.x & 127;
    int half = threadIdx.x >> 7;
    for (int t = blockIdx.x; t < ntiles; t += gridDim.x) {
        int r0 = t << 4;
        __syncthreads();
        for (int i = threadIdx.x; i < 16 * 128; i += MEGA_THREADS) {
            int rr = i >> 7, kk = i & 127;
            int gr = r0 + rr;
            sE[i] = (gr < n) ? emb[(size_t)gr * EMB + kk] : 0.0f;
        }
        __syncthreads();
        float acc[8];
#pragma unroll
        for (int rr = 0; rr < 8; rr++) acc[rr] = 0.0f;
        const float* sEr = sE + (half << 3) * 128;
#pragma unroll 4
        for (int kk = 0; kk < 128; kk++) {
            float w = __ldg(&W[kk * EMB + col]);
#pragma unroll
            for (int rr = 0; rr < 8; rr++) acc[rr] += sEr[rr * 128 + kk] * w;
        }
        float bb = __ldg(B + col), hh = __ldg(H + col);
        __syncthreads();
#pragma unroll
        for (int rr = 0; rr < 8; rr++)
            sE[((half << 3) + rr) * 128 + col] = fmaxf(acc[rr] + bb, 0.0f) * hh;
        __syncthreads();
        int wid = threadIdx.x >> 5, lane = threadIdx.x & 31;
#pragma unroll
        for (int i = 0; i < 2; i++) {
            int row = wid * 2 + i;
            float v = sE[row * 128 + lane] + sE[row * 128 + lane + 32]
                    + sE[row * 128 + lane + 64] + sE[row * 128 + lane + 96];
            for (int off = 16; off; off >>= 1) v += __shfl_down_sync(0xffffffffu, v, off);
            if (lane == 0 && r0 + row < n) s[r0 + row] = v;
        }
    }
}

__device__ void ls_dev(float* s, int n, float* sh) {
    int t = threadIdx.x;
    float m = -1e30f;
    for (int i = t; i < n; i += MEGA_THREADS) m = fmaxf(m, s[i]);
    sh[t] = m; __syncthreads();
    for (int o = 128; o; o >>= 1) { if (t < o) sh[t] = fmaxf(sh[t], sh[t + o]); __syncthreads(); }
    float mall = sh[0]; __syncthreads();
    float sum = 0.0f;
    for (int i = t; i < n; i += MEGA_THREADS) sum += expf(s[i] - mall);
    sh[t] = sum; __syncthreads();
    for (int o = 128; o; o >>= 1) { if (t < o) sh[t] += sh[t + o]; __syncthreads(); }
    float lse = mall + logf(sh[0]);
    __syncthreads();
    for (int i = t; i < n; i += MEGA_THREADS) s[i] -= lse;
}

// ---------------- the megakernel ----------------
__global__ void __launch_bounds__(MEGA_THREADS, 2) k_mega(
    const float* __restrict__ drug_structure, const float* __restrict__ protein_structure,
    const float* __restrict__ lin_drug_w, const float* __restrict__ lin_drug_b,
    const float* __restrict__ lin_pro_w, const float* __restrict__ lin_pro_b,
    const float* __restrict__ p_weight, const float* __restrict__ d_weight_i,
    const float* __restrict__ pd_weight_p, const float* __restrict__ pd_weight_d,
    const float* __restrict__ dp_weight_p,
    const float* __restrict__ WA_drug, const float* __restrict__ BA_drug, const float* __restrict__ HA_drug,
    const float* __restrict__ WB_drug, const float* __restrict__ BB_drug, const float* __restrict__ HB_drug,
    const float* __restrict__ WA_pro, const float* __restrict__ BA_pro, const float* __restrict__ HA_pro,
    const float* __restrict__ WB_pro, const float* __restrict__ BB_pro, const float* __restrict__ HB_pro,
    const float* __restrict__ WA_sim, const float* __restrict__ BA_sim, const float* __restrict__ HA_sim) {
    __shared__ float sbuf[16 * 512];
    unsigned target = 0;

    // ---- P1: build R^T + zero Gram/colsum accumulators
    {
        int nw = (gridDim.x * blockDim.x) >> 5;
        int gw = (blockIdx.x * blockDim.x + threadIdx.x) >> 5;
        int lane = threadIdx.x & 31;
        for (int r = gw; r < D_NUM; r += nw) {
            int L = g_lenR[r];
            for (int p = lane; p < L; p += 32) {
                int c = g_idxR[r * CAP_PP + p];
                int pos = atomicAdd(&g_curRT[c], 1);
                if (pos < CAP_DD) g_idxRT[c * CAP_DD + pos] = r;
            }
        }
        int stride = gridDim.x * blockDim.x;
        int gid = blockIdx.x * blockDim.x + threadIdx.x;
        for (int i = gid; i < EMB * EMB; i += stride) { g_gd[i] = 0.f; g_gp[i] = 0.f; }
        if (gid < EMB) { g_sd[gid] = 0.f; g_sp[gid] = 0.f; }
    }
    gsync(target);

    // ---- P2: sort R^T + degree scales + feature lifts + Wc (independent)
    {
        int i = blockIdx.x * blockDim.x + threadIdx.x;
        if (i < D_NUM) {
            int d;
            d = g_len2[i]; g_dinv2[i] = d > 0 ? rsqrtf((float)d) : 0.0f;
                           g_cinv2[i] = d > 0 ? 1.0f / (float)d : 0.0f;
            d = g_len4[i]; g_dinv4[i] = d > 0 ? rsqrtf((float)d) : 0.0f;
            d = g_lenR[i]; g_dinvRd[i] = d > 0 ? rsqrtf((float)d) : 0.0f;
                           g_cinvRd[i] = d > 0 ? 1.0f / (float)d : 0.0f;
        }
        if (i < P_NUM) {
            int d = g_len3[i];
            g_dinv3[i] = d > 0 ? rsqrtf((float)d) : 0.0f;
            g_cinv3[i] = d > 0 ? 1.0f / (float)d : 0.0f;
            int L = min(g_curRT[i], CAP_DD);
            g_curRT[i] = L;
            int* a = &g_idxRT[i * CAP_DD];
            for (int q = 1; q < L; q++) {
                int v = a[q]; int jj = q - 1;
                while (jj >= 0 && a[jj] > v) { a[jj + 1] = a[jj]; jj--; }
                a[jj + 1] = v;
            }
            g_dinvRp[i] = L > 0 ? rsqrtf((float)L) : 0.0f;
            g_cinvRp[i] = L > 0 ? 1.0f / (float)L : 0.0f;
        }
    }
    gemm_dev(drug_structure, D_NUM, 160, lin_drug_w, true, lin_drug_b, g_dru_str, 0, 0, sbuf);
    gemm_dev(protein_structure, P_NUM, 512, lin_pro_w, true, lin_pro_b, g_pro_str, 0, 0, sbuf);
    gemm_dev(dp_weight_p, 128, 128, pd_weight_d, true, 0, g_Wc, 0, 0, sbuf);
    gsync(target);

    // ---- P4: tower-input GEMMs (+acc inits) and neighbor means
    gemm_dev(g_dru_str, D_NUM, 128, d_weight_i, true, 0, g_curD, g_acc2, g_acc4, sbuf);
    gemm_dev(g_pro_str, P_NUM, 128, p_weight, true, 0, g_cur3, g_acc3, 0, sbuf);
    gemm_dev(g_dru_str, D_NUM, 128, pd_weight_d, true, 0, g_one_emb, g_accd, 0, sbuf);
    gemm_dev(g_pro_str, P_NUM, 128, pd_weight_p, true, 0, g_two_emb, g_accp, 0, sbuf);
    spmm_dev(g_idx2, g_len2, CAP_DD, g_cinv2, 0, g_dru_str, g_nei2, 0, 0, 0.f, 0, 0, D_NUM);
    spmm_dev(g_idx3, g_len3, CAP_PP, g_cinv3, 0, g_pro_str, g_nei3, 0, 0, 0.f, 0, 0, P_NUM);
    gsync(target);

    // ---- P5: GCN layer 1 + cross-domain neighbor means with fused mix
    spmm_dev(g_idx2, g_len2, CAP_DD, g_dinv2, g_dinv2, g_curD, g_x2a, g_acc2, 0, 0.f, 0, 0, D_NUM);
    spmm_dev(g_idx3, g_len3, CAP_PP, g_dinv3, g_dinv3, g_cur3, g_x3a, g_acc3, 0, 0.f, 0, 0, P_NUM);
    spmm_dev(g_idx4, g_len4, CAP_DD, g_dinv4, g_dinv4, g_curD, g_x4a, g_acc4, 0, 0.f, 0, 0, D_NUM);
    spmm_dev(g_idxR, g_lenR, CAP_PP, g_cinvRd, 0, g_nei3, 0, 0, 0, 0.f, g_dru_str, g_one_all, D_NUM);
    spmm_dev(g_idxRT, g_curRT, CAP_DD, g_cinvRp, 0, g_nei2, 0, 0, 0, 0.f, g_pro_str, g_tmpp, P_NUM);
    gsync(target);

    // ---- P6: GCN layer 2 + two_all GEMM
    spmm_dev(g_idx2, g_len2, CAP_DD, g_dinv2, g_dinv2, g_x2a, g_x2b, g_acc2, 0, 0.f, 0, 0, D_NUM);
    spmm_dev(g_idx3, g_len3, CAP_PP, g_dinv3, g_dinv3, g_x3a, g_x3b, g_acc3, 0, 0.f, 0, 0, P_NUM);
    spmm_dev(g_idx4, g_len4, CAP_DD, g_dinv4, g_dinv4, g_x4a, g_x4b, g_acc4, 0, 0.f, 0, 0, D_NUM);
    gemm_dev(g_tmpp, P_NUM, 128, g_Wc, false, 0, g_two_all, 0, 0, sbuf);
    gsync(target);

    // ---- P7: GCN layer 3 (finalize towers) + bipartite step 1
    spmm_dev(g_idx2, g_len2, CAP_DD, g_dinv2, g_dinv2, g_x2b, 0, g_acc2, g_emb2, 0.25f, 0, 0, D_NUM);
    spmm_dev(g_idx3, g_len3, CAP_PP, g_dinv3, g_dinv3, g_x3b, 0, g_acc3, g_emb3, 0.25f, 0, 0, P_NUM);
    spmm_dev(g_idx4, g_len4, CAP_DD, g_dinv4, g_dinv4, g_x4b, 0, g_acc4, g_emb4, 0.25f, 0, 0, D_NUM);
    spmm_dev(g_idxR, g_lenR, CAP_PP, g_dinvRd, g_dinvRp, g_two_all, g_bd1, g_accd, 0, 0.f, 0, 0, D_NUM);
    spmm_dev(g_idxRT, g_curRT, CAP_DD, g_dinvRp, g_dinvRd, g_one_emb, g_bp1, 0, 0, 0.f, 0, 0, P_NUM);
    spmm_dev(g_idxRT, g_curRT, CAP_DD, g_dinvRp, g_dinvRd, g_one_all, g_bpx, g_accp, 0, 0.f, 0, 0, P_NUM);
    spmm_dev(g_idxR, g_lenR, CAP_PP, g_dinvRd, g_dinvRp, g_two_emb, g_bdx, 0, 0, 0.f, 0, 0, D_NUM);
    gsync(target);

    // ---- P8: bipartite step 2 + tower attention heads (overlap)
    spmm_dev(g_idxRT, g_curRT, CAP_DD, g_dinvRp, g_dinvRd, g_bd1, g_bp2, 0, 0, 0.f, 0, 0, P_NUM);
    spmm_dev(g_idxR, g_lenR, CAP_PP, g_dinvRd, g_dinvRp, g_bp1, 0, g_accd, 0, 0.f, 0, 0, D_NUM);
    spmm_dev(g_idxRT, g_curRT, CAP_DD, g_dinvRp, g_dinvRd, g_bdx, 0, g_accp, 0, 0.f, 0, 0, P_NUM);
    spmm_dev(g_idxR, g_lenR, CAP_PP, g_dinvRd, g_dinvRp, g_bpx, g_bdy, 0, 0, 0.f, 0, 0, D_NUM);
    att_dev(g_emb2, WB_drug, BB_drug, HB_drug, g_wdrel, D_NUM, sbuf);
    att_dev(g_emb3, WB_pro, BB_pro, HB_pro, g_wprel, P_NUM, sbuf);
    att_dev(g_emb4, WA_sim, BA_sim, HA_sim, g_wdsim, D_NUM, sbuf);
    gsync(target);

    // ---- P9: bipartite step 3
    spmm_dev(g_idxR, g_lenR, CAP_PP, g_dinvRd, g_dinvRp, g_bp2, 0, g_accd, g_dru_int, 0.25f, 0, 0, D_NUM);
    spmm_dev(g_idxRT, g_curRT, CAP_DD, g_dinvRp, g_dinvRd, g_bdy, 0, g_accp, g_pro_int, 0.25f, 0, 0, P_NUM);
    gsync(target);

    // ---- P10: remaining attention heads
    att_dev(g_dru_int, WA_drug, BA_drug, HA_drug, g_wdrug, D_NUM, sbuf);
    att_dev(g_pro_int, WA_pro, BA_pro, HA_pro, g_wpro, P_NUM, sbuf);
    gsync(target);

    // ---- P11: log-softmax
    if (blockIdx.x < 5) {
        float* s; int n;
        switch (blockIdx.x) {
            case 0: s = g_wdrug; n = D_NUM; break;
            case 1: s = g_wpro;  n = P_NUM; break;
            case 2: s = g_wdrel; n = D_NUM; break;
            case 3: s = g_wprel; n = P_NUM; break;
            default:s = g_wdsim; n = D_NUM; break;
        }
        ls_dev(s, n, sbuf);
    }
    gsync(target);

    // ---- P12: weighted combine
    {
        int stride = gridDim.x * blockDim.x;
        for (int i = blockIdx.x * blockDim.x + threadIdx.x; i < DB + PB; i += stride) {
            if (i < DB) {
                int r = i >> 7;
                float wa = g_wdrug[r], wb = g_wdrel[r], wc = g_wdsim[r];
                float a = wa / (wa + wb + wc);
                float b = wb / (a + wb + wc);
                float c = 1.0f - a - b;
                g_fin_d[i] = a * g_dru_int[i] + b * g_emb2[i] + c * g_emb4[i];
            } else {
                int j = i - DB;
                int r = j >> 7;
                float wa = g_wpro[r], wb = g_wprel[r];
                float pa = wa / (wa + wb);
                g_fin_p[j] = pa * g_pro_int[j] + (1.0f - pa) * g_emb3[j];
            }
        }
    }
    gsync(target);

    // ---- P13: Gram matrices + column sums (blocks 0..127)
    if (blockIdx.x < 128) {
        const float* X; int n, brel, nblk;
        float* gG; float* gS;
        if (blockIdx.x < 32) { X = g_fin_d; n = D_NUM; brel = blockIdx.x;      nblk = 32; gG = g_gd; gS = g_sd; }
        else                 { X = g_fin_p; n = P_NUM; brel = blockIdx.x - 32; nblk = 96; gG = g_gp; gS = g_sp; }
        int ntiles = (n + 15) >> 4;
        int k0 = (threadIdx.x & 15) * 8, l0 = (threadIdx.x >> 4) * 8;
        float accG[8][8];
#pragma unroll
        for (int i = 0; i < 8; i++)
#pragma unroll
            for (int j = 0; j < 8; j++) accG[i][j] = 0.f;
        float cs = 0.f;
        for (int t = brel; t < ntiles; t += nblk) {
            int r0 = t << 4;
            __syncthreads();
            for (int i = threadIdx.x; i < 16 * 128; i += MEGA_THREADS) {
                int rr = i >> 7, kk = i & 127;
                int gr = r0 + rr;
                sbuf[rr * 132 + kk] = (gr < n) ? X[(size_t)gr * EMB + kk] : 0.f;
            }
            __syncthreads();
#pragma unroll 4
            for (int r = 0; r < 16; r++) {
                const float* row = &sbuf[r * 132];
                float4 a0 = *(const float4*)(row + k0);
                float4 a1 = *(const float4*)(row + k0 + 4);
                float4 b0 = *(const float4*)(row + l0);
                float4 b1 = *(const float4*)(row + l0 + 4);
                float av[8] = {a0.x, a0.y, a0.z, a0.w, a1.x, a1.y, a1.z, a1.w};
                float bv[8] = {b0.x, b0.y, b0.z, b0.w, b1.x, b1.y, b1.z, b1.w};
#pragma unroll
                for (int i = 0; i < 8; i++)
#pragma unroll
                    for (int j = 0; j < 8; j++) accG[i][j] += av[i] * bv[j];
            }
            if (threadIdx.x < 128) {
                float c = 0.f;
                for (int r = 0; r < 16; r++) c += sbuf[r * 132 + threadIdx.x];
                cs += c;
            }
        }
#pragma unroll
        for (int i = 0; i < 8; i++)
#pragma unroll
            for (int j = 0; j < 8; j++)
                atomicAdd(&gG[(k0 + i) * EMB + (l0 + j)], accG[i][j]);
        if (threadIdx.x < 128) atomicAdd(&gS[threadIdx.x], cs);
    }
    gsync(target);

    // ---- P14: reduce stats -> g_musig (block 0 only; others exit)
    if (blockIdx.x == 0) {
        double* sd = (double*)sbuf;
        double acc = 0.0;
        for (int i = threadIdx.x; i < EMB * EMB; i += MEGA_THREADS)
            acc += (double)g_gd[i] * (double)g_gp[i];
        sd[threadIdx.x] = acc; __syncthreads();
        for (int o = 128; o; o >>= 1) { if (threadIdx.x < o) sd[threadIdx.x] += sd[threadIdx.x + o]; __syncthreads(); }
        double sumsq = sd[0]; __syncthreads();
        double a2 = (threadIdx.x < EMB) ? (double)g_sd[threadIdx.x] * (double)g_sp[threadIdx.x] : 0.0;
        sd[threadIdx.x] = a2; __syncthreads();
        for (int o = 128; o; o >>= 1) { if (threadIdx.x < o) sd[threadIdx.x] += sd[threadIdx.x + o]; __syncthreads(); }
        if (threadIdx.x == 0) {
            double sumy = sd[0];
            const double n = (double)D_NUM * (double)P_NUM;
            double mean = sumy / n;
            double var = (sumsq - sumy * sumy / n) / (n - 1.0);
            g_musig = make_float2((float)mean, (float)(1.0 / sqrt(var)));
        }
    }
}

// ---------------- final GEMM with fused standardize+sigmoid ----------------
__global__ void __launch_bounds__(256) k_final_gemm(float* __restrict__ out) {
    __shared__ __align__(16) float sA[32 * 132];
    __shared__ __align__(16) float sB[32 * 132];
    float2 ms = g_musig;
    float mu = ms.x, istd = ms.y;
    int bi = blockIdx.y * 128, bj = blockIdx.x * 128;
    int t = threadIdx.x;
    int tx = t & 15, ty = t >> 4;
    int m0 = ty * 8, n0 = tx * 8;
    float acc[8][8];
#pragma unroll
    for (int i = 0; i < 8; i++)
#pragma unroll
        for (int j = 0; j < 8; j++) acc[i][j] = 0.0f;

    for (int k0 = 0; k0 < EMB; k0 += 32) {
#pragma unroll
        for (int it = 0; it < 4; it++) {
            int e = t + it * 256;
            int rr = e >> 3, kv = e & 7;
            int gi = bi + rr, gj = bj + rr;
            float4 va = (gi < D_NUM) ? *(const float4*)&g_fin_d[(size_t)gi * EMB + k0 + kv * 4]
                                     : make_float4(0.f, 0.f, 0.f, 0.f);
            float4 vb = (gj < P_NUM) ? *(const float4*)&g_fin_p[(size_t)gj * EMB + k0 + kv * 4]
                                     : make_float4(0.f, 0.f, 0.f, 0.f);
            sA[(kv * 4 + 0) * 132 + rr] = va.x;
            sA[(kv * 4 + 1) * 132 + rr] = va.y;
            sA[(kv * 4 + 2) * 132 + rr] = va.z;
            sA[(kv * 4 + 3) * 132 + rr] = va.w;
            sB[(kv * 4 + 0) * 132 + rr] = vb.x;
            sB[(kv * 4 + 1) * 132 + rr] = vb.y;
            sB[(kv * 4 + 2) * 132 + rr] = vb.z;
            sB[(kv * 4 + 3) * 132 + rr] = vb.w;
        }
        __syncthreads();
#pragma unroll
        for (int kk = 0; kk < 32; kk++) {
            const float* pa = &sA[kk * 132 + m0];
            const float* pb = &sB[kk * 132 + n0];
            float4 a0 = *(const float4*)pa;
            float4 a1 = *(const float4*)(pa + 4);
            float4 b0 = *(const float4*)pb;
            float4 b1 = *(const float4*)(pb + 4);
            float ra[8] = {a0.x, a0.y, a0.z, a0.w, a1.x, a1.y, a1.z, a1.w};
            float rb[8] = {b0.x, b0.y, b0.z, b0.w, b1.x, b1.y, b1.z, b1.w};
#pragma unroll
            for (int i = 0; i < 8; i++)
#pragma unroll
                for (int j = 0; j < 8; j++) acc[i][j] += ra[i] * rb[j];
        }
        __syncthreads();
    }
#pragma unroll
    for (int i = 0; i < 8; i++) {
        int gi = bi + m0 + i;
        if (gi < D_NUM) {
#pragma unroll
            for (int j = 0; j < 8; j++) {
                int gj = bj + n0 + j;
                if (gj < P_NUM) {
                    float z = (acc[i][j] - mu) * istd;
                    out[(size_t)gi * P_NUM + gj] = __fdividef(1.0f, 1.0f + __expf(-z));
                }
            }
        }
    }
}

// ---------------- host launcher ----------------
extern "C" void kernel_launch(void* const* d_in, const int* in_sizes, int n_in,
                              void* d_out, int out_size) {
    const float* A                 = (const float*)d_in[0];
    const float* drug_structure    = (const float*)d_in[1];
    const float* protein_structure = (const float*)d_in[2];
    const float* lin_drug_w = (const float*)d_in[3];
    const float* lin_drug_b = (const float*)d_in[4];
    const float* lin_pro_w  = (const float*)d_in[5];
    const float* lin_pro_b  = (const float*)d_in[6];
    const float* p_weight   = (const float*)d_in[7];
    const float* d_weight_i = (const float*)d_in[8];
    const float* pd_weight_p = (const float*)d_in[9];
    const float* pd_weight_d = (const float*)d_in[10];
    const float* dp_weight_p = (const float*)d_in[11];
    const float* WA_drug = (const float*)d_in[12];
    const float* BA_drug = (const float*)d_in[13];
    const float* HA_drug = (const float*)d_in[14];
    const float* WB_drug = (const float*)d_in[15];
    const float* BB_drug = (const float*)d_in[16];
    const float* HB_drug = (const float*)d_in[17];
    const float* WA_pro = (const float*)d_in[18];
    const float* BA_pro = (const float*)d_in[19];
    const float* HA_pro = (const float*)d_in[20];
    const float* WB_pro = (const float*)d_in[21];
    const float* BB_pro = (const float*)d_in[22];
    const float* HB_pro = (const float*)d_in[23];
    const float* WA_sim = (const float*)d_in[24];
    const float* BA_sim = (const float*)d_in[25];
    const float* HA_sim = (const float*)d_in[26];
    float* out = (float*)d_out;
    (void)in_sizes; (void)n_in; (void)out_size;

    void* tp;
    cudaGetSymbolAddress(&tp, g_curRT);  void* p_curRT  = tp;
    cudaGetSymbolAddress(&tp, g_barcnt); void* p_barcnt = tp;

    cudaMemsetAsync(p_curRT, 0, P_NUM * sizeof(int), 0);
    cudaMemsetAsync(p_barcnt, 0, sizeof(unsigned), 0);

    k_ell_all<<<9000, 256>>>(A);

    k_mega<<<MEGA_BLKS, MEGA_THREADS>>>(
        drug_structure, protein_structure,
        lin_drug_w, lin_drug_b, lin_pro_w, lin_pro_b,
        p_weight, d_weight_i, pd_weight_p, pd_weight_d, dp_weight_p,
        WA_drug, BA_drug, HA_drug,
        WB_drug, BB_drug, HB_drug,
        WA_pro, BA_pro, HA_pro,
        WB_pro, BB_pro, HB_pro,
        WA_sim, BA_sim, HA_sim);

    dim3 fg((P_NUM + 127) / 128, (D_NUM + 127) / 128);
    k_final_gemm<<<fg, 256>>>(out);
}